// round 15
// baseline (speedup 1.0000x reference)
#include <cuda_runtime.h>
#include <cuda_fp16.h>
#include <math.h>
#include <stdint.h>

// Problem constants
#define BATCH 2
#define SEQ   2048
#define EMB   1024
#define NHEAD 16
#define HDIM  64
#define MROWS (BATCH*SEQ)   // 4096

// ---------------------------------------------------------------------------
// Scratch (device globals; no runtime allocation allowed) — all fp16
// ---------------------------------------------------------------------------
__device__ __half g_Q[MROWS * EMB];
__device__ __half g_K[MROWS * EMB];
__device__ __half g_VT[EMB * MROWS];   // V projection output, TRANSPOSED [emb][token]
__device__ __half g_A[MROWS * EMB];    // attention output O
// fp16-pre-rounded copies of inputs and weights
__device__ __half g_QR[MROWS * EMB];
__device__ __half g_KR[MROWS * EMB];
__device__ __half g_VR[MROWS * EMB];
__device__ __half g_WQ[EMB * EMB];
__device__ __half g_WK[EMB * EMB];
__device__ __half g_WV[EMB * EMB];
__device__ __half g_WO[EMB * EMB];

// ---------------------------------------------------------------------------
// Helpers
// ---------------------------------------------------------------------------
__device__ __forceinline__ uint32_t smem_u32(const void* p) {
    uint32_t a;
    asm("{ .reg .u64 t; cvta.to.shared.u64 t, %1; cvt.u32.u64 %0, t; }"
        : "=r"(a) : "l"(p));
    return a;
}
__device__ __forceinline__ float fexp2(float x) {
    float r;
    asm("ex2.approx.ftz.f32 %0, %1;" : "=f"(r) : "f"(x));
    return r;
}
__device__ __forceinline__ void mma_f16(float* c, const uint32_t* a, const uint32_t* b) {
    asm volatile(
        "mma.sync.aligned.m16n8k16.row.col.f32.f16.f16.f32 "
        "{%0,%1,%2,%3}, {%4,%5,%6,%7}, {%8,%9}, {%0,%1,%2,%3};"
        : "+f"(c[0]), "+f"(c[1]), "+f"(c[2]), "+f"(c[3])
        : "r"(a[0]), "r"(a[1]), "r"(a[2]), "r"(a[3]), "r"(b[0]), "r"(b[1]));
}
__device__ __forceinline__ uint32_t packh2(float x, float y) {
    __half2 h = __floats2half2_rn(x, y);
    return *(uint32_t*)&h;
}

// ldmatrix x4: four 8x8 b16 tiles (native fp16)
#define LDSM_X4(r, addr) \
    asm volatile("ldmatrix.sync.aligned.m8n8.x4.shared.b16 {%0,%1,%2,%3}, [%4];" \
        : "=r"((r)[0]), "=r"((r)[1]), "=r"((r)[2]), "=r"((r)[3]) : "r"(addr))

#define CP_ASYNC16(dst_u32, src_ptr) \
    asm volatile("cp.async.cg.shared.global [%0], [%1], 16;" \
                 :: "r"(dst_u32), "l"(src_ptr))
#define CP_COMMIT() asm volatile("cp.async.commit_group;")
#define CP_WAIT(n)  asm volatile("cp.async.wait_group %0;" :: "n"(n))

// ---------------------------------------------------------------------------
// Prologue: round tensors to fp16 (rn) into scratch. blockIdx.y picks tensor.
// ---------------------------------------------------------------------------
__global__ __launch_bounds__(256) void round_f16_all(
    const float* q, const float* k, const float* v,
    const float* wq, const float* wk, const float* wv, const float* wo)
{
    const float* src; __half* dst; int n;
    switch (blockIdx.y) {
        case 0: src = q;  dst = g_QR; n = MROWS * EMB; break;
        case 1: src = k;  dst = g_KR; n = MROWS * EMB; break;
        case 2: src = v;  dst = g_VR; n = MROWS * EMB; break;
        case 3: src = wq; dst = g_WQ; n = EMB * EMB;   break;
        case 4: src = wk; dst = g_WK; n = EMB * EMB;   break;
        case 5: src = wv; dst = g_WV; n = EMB * EMB;   break;
        default: src = wo; dst = g_WO; n = EMB * EMB;  break;
    }
    int n4 = n >> 2;
    for (int i = blockIdx.x * blockDim.x + threadIdx.x; i < n4;
         i += gridDim.x * blockDim.x) {
        float4 x = ((const float4*)src)[i];
        __half2* d = (__half2*)(dst + (size_t)i * 4);
        d[0] = __floats2half2_rn(x.x, x.y);
        d[1] = __floats2half2_rn(x.z, x.w);
    }
}

// ---------------------------------------------------------------------------
// GEMM core (fp16 operands, fp32 accum): C = A[M,K] @ W[N,K]^T + bias.
// 128x128x64 tile, 256 thr, 3-stage cp.async ring, single barrier per chunk,
// next-stage loads issued MID-CHUNK. mode: 0 fp32 C, 1 fp16 C, 2 fp16 C^T.
// ---------------------------------------------------------------------------
#define GBM 128
#define GBN 128
#define GBK 64
#define PADH 72                                   // halfs per smem row
#define GSTG_HALFS (2 * GBM * PADH)               // A+B per stage = 18432
#define GEMM_SMEM_BYTES (3 * GSTG_HALFS * 2)      // 110592

__device__ __forceinline__ void gemm_core(
    const __half* __restrict__ A, const __half* __restrict__ W,
    const float* __restrict__ bias, float* __restrict__ Cf,
    __half* __restrict__ Ch, int mode)
{
    extern __shared__ __half hsmem[];
    const int M = MROWS, N = EMB, K = EMB;

    const int tid  = threadIdx.x;
    const int lane = tid & 31;
    const int warp = tid >> 5;
    const int bm = blockIdx.y * GBM;
    const int bn = blockIdx.x * GBN;

    const int wm = (warp >> 2) * 64;
    const int wn = (warp & 3) * 32;
    const int gid = lane >> 2;
    const int tig = lane & 3;

    // ldmatrix per-lane half offsets
    const int aoff = (wm + (lane & 15)) * PADH + (lane >> 4) * 8;
    const int boff = (wn + (lane & 7)) * PADH + (lane >> 3) * 8;

    float acc[4][4][4];
#pragma unroll
    for (int mt = 0; mt < 4; mt++)
#pragma unroll
        for (int nt = 0; nt < 4; nt++)
#pragma unroll
            for (int r = 0; r < 4; r++) acc[mt][nt][r] = 0.f;

    auto load_stage = [&](int s, int k0) {
        __half* As = hsmem + s * GSTG_HALFS;
        __half* Bs = As + GBM * PADH;
#pragma unroll
        for (int p = 0; p < 4; p++) {
            int idx = tid + p * 256;        // 0..1023
            int row = idx >> 3;             // 0..127
            int c   = (idx & 7) * 8;        // halfs 0..56
            CP_ASYNC16(smem_u32(As + row * PADH + c),
                       A + (size_t)(bm + row) * K + k0 + c);
            CP_ASYNC16(smem_u32(Bs + row * PADH + c),
                       W + (size_t)(bn + row) * K + k0 + c);
        }
        CP_COMMIT();
    };

    auto compute_half = [&](uint32_t abase, uint32_t bbase, int ks2) {
        uint32_t bfr[4][4];
#pragma unroll
        for (int nt = 0; nt < 4; nt++)
            LDSM_X4(bfr[nt], bbase + 2u * (boff + nt * 8 * PADH + ks2 * 32));
#pragma unroll
        for (int ksl = 0; ksl < 2; ksl++) {
            uint32_t afr[4][4];
#pragma unroll
            for (int mt = 0; mt < 4; mt++)
                LDSM_X4(afr[mt],
                        abase + 2u * (aoff + mt * 16 * PADH + ks2 * 32 + ksl * 16));
#pragma unroll
            for (int mt = 0; mt < 4; mt++)
#pragma unroll
                for (int nt = 0; nt < 4; nt++)
                    mma_f16(acc[mt][nt], afr[mt], &bfr[nt][ksl * 2]);
        }
    };

    const int nchunk = K / GBK;   // 16
    load_stage(0, 0);
    load_stage(1, GBK);

    for (int i = 0; i < nchunk; i++) {
        CP_WAIT(1);
        __syncthreads();
        const uint32_t abase = smem_u32(hsmem + (i % 3) * GSTG_HALFS);
        const uint32_t bbase = abase + GBM * PADH * 2;

        compute_half(abase, bbase, 0);
        if (i + 2 < nchunk) load_stage((i + 2) % 3, (i + 2) * GBK);
        compute_half(abase, bbase, 1);
    }

#pragma unroll
    for (int nt = 0; nt < 4; nt++) {
        const int c0 = bn + wn + nt * 8 + tig * 2;
        const float b0 = bias[c0], b1 = bias[c0 + 1];
#pragma unroll
        for (int mt = 0; mt < 4; mt++) {
            const int r0 = bm + wm + mt * 16 + gid;
            float2 v0 = make_float2(acc[mt][nt][0] + b0, acc[mt][nt][1] + b1);
            float2 v1 = make_float2(acc[mt][nt][2] + b0, acc[mt][nt][3] + b1);
            if (mode == 0) {
                *(float2*)(Cf + (size_t)r0 * N + c0) = v0;
                *(float2*)(Cf + (size_t)(r0 + 8) * N + c0) = v1;
            } else if (mode == 1) {
                *(__half2*)(Ch + (size_t)r0 * N + c0) = __floats2half2_rn(v0.x, v0.y);
                *(__half2*)(Ch + (size_t)(r0 + 8) * N + c0) = __floats2half2_rn(v1.x, v1.y);
            } else {   // transposed: C[col][row], ldc = M
                Ch[(size_t)c0 * M + r0]           = __float2half_rn(v0.x);
                Ch[(size_t)(c0 + 1) * M + r0]     = __float2half_rn(v0.y);
                Ch[(size_t)c0 * M + r0 + 8]       = __float2half_rn(v1.x);
                Ch[(size_t)(c0 + 1) * M + r0 + 8] = __float2half_rn(v1.y);
            }
        }
    }
}

// Fused Q/K/V projection: blockIdx.z selects tensor.
__global__ __launch_bounds__(256, 2) void gemm_qkv(
    const float* __restrict__ bq, const float* __restrict__ bk,
    const float* __restrict__ bv)
{
    switch (blockIdx.z) {
        case 0: gemm_core(g_QR, g_WQ, bq, nullptr, g_Q, 1); break;
        case 1: gemm_core(g_KR, g_WK, bk, nullptr, g_K, 1); break;
        default: gemm_core(g_VR, g_WV, bv, nullptr, g_VT, 2); break;
    }
}

// Output projection (fp32 out).
__global__ __launch_bounds__(256, 2) void gemm_out(
    const float* __restrict__ bo, float* __restrict__ out)
{
    gemm_core(g_A, g_WO, bo, out, nullptr, 0);
}

// ---------------------------------------------------------------------------
// Flash attention, mma.sync fp16 (fp32 accum), 3-slot KV ring, single barrier
// per tile, KV refill mid-tile, P kept in registers (S C-frag == PV A-frag).
// CTA: 128 q rows, 128 threads, 4 warps (32 q rows each, mt=2).
// NOW 3 CTAs/SM (launch_bounds cap 170 regs) for +50% latency cover.
// Slot: K rows [0,64) key-major; V^T rows [64,128) hd-major. Q stages slot2.
// ---------------------------------------------------------------------------
#define AQ   128
#define AKV  64
#define APADH 72
#define SLOT_HALFS (128 * APADH)                // 9216 halfs = 18432 B
#define ATTN_SMEM_BYTES (3 * SLOT_HALFS * 2)    // 55296

__global__ __launch_bounds__(128, 3) void flash_attn_mma()
{
    extern __shared__ __half hdsm[];

    const int qt = blockIdx.x;
    const int h  = blockIdx.y;
    const int b  = blockIdx.z;

    const __half* Qb = g_Q + ((size_t)b * SEQ + qt * AQ) * EMB + h * HDIM;
    const __half* Kb = g_K + (size_t)b * SEQ * EMB + h * HDIM;
    const __half* Vtb = g_VT + (size_t)(h * HDIM) * MROWS + (size_t)b * SEQ;
    __half*       Ob = g_A + ((size_t)b * SEQ + qt * AQ) * EMB + h * HDIM;

    const int tid  = threadIdx.x;
    const int lane = tid & 31;
    const int warp = tid >> 5;
    const int gid  = lane >> 2;
    const int tig  = lane & 3;
    const int wm   = warp * 32;

    // ldmatrix per-lane half offsets
    const int aoff = (wm + (lane & 15)) * APADH + (lane >> 4) * 8;   // A rows (q)
    const int boff = (lane & 7) * APADH + (lane >> 3) * 8;           // B rows

    auto load_kv = [&](__half* base, int kt) {
        const __half* Kt = Kb + (size_t)kt * AKV * EMB;
        const __half* Vt = Vtb + (size_t)kt * AKV;
#pragma unroll
        for (int p = 0; p < 4; p++) {
            int idx = tid + p * 128;       // 0..511
            int row = idx >> 3;            // 0..63
            int c   = (idx & 7) * 8;       // halfs
            CP_ASYNC16(smem_u32(base + row * APADH + c),
                       Kt + (size_t)row * EMB + c);
            CP_ASYNC16(smem_u32(base + (AKV + row) * APADH + c),
                       Vt + (size_t)row * MROWS + c);
        }
        CP_COMMIT();
    };

    // Prologue: Q -> slot2, KV0 -> slot0, KV1 -> slot1 (all async).
    __half* slot2 = hdsm + 2 * SLOT_HALFS;
#pragma unroll
    for (int p = 0; p < 8; p++) {
        int idx = tid + p * 128;           // 0..1023
        int row = idx >> 3;                // 0..127
        int c   = (idx & 7) * 8;
        CP_ASYNC16(smem_u32(slot2 + row * APADH + c),
                   Qb + (size_t)row * EMB + c);
    }
    CP_COMMIT();
    load_kv(hdsm, 0);
    load_kv(hdsm + SLOT_HALFS, 1);

    CP_WAIT(2);            // Q resident
    __syncthreads();

    // Hoist Q fragments via ldmatrix; scale by softmax*log2e in fp32, repack.
    const float qscale = 0.125f * 1.4426950408889634f;
    const uint32_t qsbase = smem_u32(slot2);
    uint32_t qfr[2][4][4];
#pragma unroll
    for (int mt = 0; mt < 2; mt++)
#pragma unroll
        for (int ks = 0; ks < 4; ks++) {
            uint32_t t[4];
            LDSM_X4(t, qsbase + 2u * (aoff + mt * 16 * APADH + ks * 16));
#pragma unroll
            for (int j = 0; j < 4; j++) {
                float2 f = __half22float2(*(__half2*)&t[j]);
                qfr[mt][ks][j] = packh2(f.x * qscale, f.y * qscale);
            }
        }
    __syncthreads();       // all warps done with slot2 before KV2 refill

    float oacc[2][8][4];
#pragma unroll
    for (int mt = 0; mt < 2; mt++)
#pragma unroll
        for (int nt = 0; nt < 8; nt++)
#pragma unroll
            for (int r = 0; r < 4; r++) oacc[mt][nt][r] = 0.f;
    float mrow[2][2], lrow[2][2];
#pragma unroll
    for (int mt = 0; mt < 2; mt++) {
        mrow[mt][0] = -1e30f; mrow[mt][1] = -1e30f;
        lrow[mt][0] = 0.f;    lrow[mt][1] = 0.f;
    }

    const int ntile = SEQ / AKV;   // 32
    for (int kt = 0; kt < ntile; kt++) {
        CP_WAIT(1);        // KV_kt resident
        __syncthreads();
        const uint32_t kbase = smem_u32(hdsm + (kt % 3) * SLOT_HALFS);
        const uint32_t vbase = kbase + AKV * APADH * 2;

        // S = Q K^T (k = hd = 64 -> 2 x k32). Fragments get the LSU first.
        float sacc[2][8][4];
#pragma unroll
        for (int mt = 0; mt < 2; mt++)
#pragma unroll
            for (int nt = 0; nt < 8; nt++)
#pragma unroll
                for (int r = 0; r < 4; r++) sacc[mt][nt][r] = 0.f;

#pragma unroll
        for (int ks2 = 0; ks2 < 2; ks2++) {
#pragma unroll
            for (int nt = 0; nt < 8; nt++) {
                uint32_t bf[4];
                LDSM_X4(bf, kbase + 2u * (boff + nt * 8 * APADH + ks2 * 32));
                mma_f16(sacc[0][nt], qfr[0][ks2 * 2], bf);
                mma_f16(sacc[1][nt], qfr[1][ks2 * 2], bf);
                mma_f16(sacc[0][nt], qfr[0][ks2 * 2 + 1], bf + 2);
                mma_f16(sacc[1][nt], qfr[1][ks2 * 2 + 1], bf + 2);
            }
        }

        // Mid-tile refill: issue KV_{kt+2} while softmax + PV cover latency.
        if (kt + 2 < ntile) load_kv(hdsm + ((kt + 2) % 3) * SLOT_HALFS, kt + 2);

        // Online softmax (exp2 domain, fp32) + build PV A-fragments directly.
        uint32_t pa[2][4][4];    // [mt][k16-tile][frag]
#pragma unroll
        for (int mt = 0; mt < 2; mt++) {
            float mx0 = -1e30f, mx1 = -1e30f;
#pragma unroll
            for (int nt = 0; nt < 8; nt++) {
                mx0 = fmaxf(mx0, fmaxf(sacc[mt][nt][0], sacc[mt][nt][1]));
                mx1 = fmaxf(mx1, fmaxf(sacc[mt][nt][2], sacc[mt][nt][3]));
            }
            mx0 = fmaxf(mx0, __shfl_xor_sync(0xffffffffu, mx0, 1));
            mx0 = fmaxf(mx0, __shfl_xor_sync(0xffffffffu, mx0, 2));
            mx1 = fmaxf(mx1, __shfl_xor_sync(0xffffffffu, mx1, 1));
            mx1 = fmaxf(mx1, __shfl_xor_sync(0xffffffffu, mx1, 2));

            float mn0 = fmaxf(mrow[mt][0], mx0), mn1 = fmaxf(mrow[mt][1], mx1);
            float corr0 = fexp2(mrow[mt][0] - mn0), corr1 = fexp2(mrow[mt][1] - mn1);
            float s0 = 0.f, s1 = 0.f;
#pragma unroll
            for (int nt = 0; nt < 8; nt++) {
                sacc[mt][nt][0] = fexp2(sacc[mt][nt][0] - mn0);
                sacc[mt][nt][1] = fexp2(sacc[mt][nt][1] - mn0);
                sacc[mt][nt][2] = fexp2(sacc[mt][nt][2] - mn1);
                sacc[mt][nt][3] = fexp2(sacc[mt][nt][3] - mn1);
                s0 += sacc[mt][nt][0] + sacc[mt][nt][1];
                s1 += sacc[mt][nt][2] + sacc[mt][nt][3];
            }
            s0 += __shfl_xor_sync(0xffffffffu, s0, 1);
            s0 += __shfl_xor_sync(0xffffffffu, s0, 2);
            s1 += __shfl_xor_sync(0xffffffffu, s1, 1);
            s1 += __shfl_xor_sync(0xffffffffu, s1, 2);
            lrow[mt][0] = lrow[mt][0] * corr0 + s0;  mrow[mt][0] = mn0;
            lrow[mt][1] = lrow[mt][1] * corr1 + s1;  mrow[mt][1] = mn1;
#pragma unroll
            for (int nt = 0; nt < 8; nt++) {
                oacc[mt][nt][0] *= corr0; oacc[mt][nt][1] *= corr0;
                oacc[mt][nt][2] *= corr1; oacc[mt][nt][3] *= corr1;
            }

            // PV A-fragments: S C-frag layout == PV A-frag layout.
#pragma unroll
            for (int kk = 0; kk < 4; kk++) {
                pa[mt][kk][0] = packh2(sacc[mt][2 * kk][0],     sacc[mt][2 * kk][1]);
                pa[mt][kk][1] = packh2(sacc[mt][2 * kk][2],     sacc[mt][2 * kk][3]);
                pa[mt][kk][2] = packh2(sacc[mt][2 * kk + 1][0], sacc[mt][2 * kk + 1][1]);
                pa[mt][kk][3] = packh2(sacc[mt][2 * kk + 1][2], sacc[mt][2 * kk + 1][3]);
            }
        }

        // O += P V : A = pa (registers), B = V^T (hd-major) via ldmatrix.
#pragma unroll
        for (int ks2 = 0; ks2 < 2; ks2++) {
#pragma unroll
            for (int nt = 0; nt < 8; nt++) {
                uint32_t vf[4];
                LDSM_X4(vf, vbase + 2u * (boff + nt * 8 * APADH + ks2 * 32));
                mma_f16(oacc[0][nt], pa[0][2 * ks2], vf);
                mma_f16(oacc[1][nt], pa[1][2 * ks2], vf);
                mma_f16(oacc[0][nt], pa[0][2 * ks2 + 1], vf + 2);
                mma_f16(oacc[1][nt], pa[1][2 * ks2 + 1], vf + 2);
            }
        }
        // No bottom barrier: next iteration's top barrier carries ring safety.
    }

    // Epilogue: normalize, round to fp16 (feeds final GEMM), write.
#pragma unroll
    for (int mt = 0; mt < 2; mt++) {
        const float inv0 = 1.0f / lrow[mt][0], inv1 = 1.0f / lrow[mt][1];
        const int r0 = wm + mt * 16 + gid, r1 = r0 + 8;
#pragma unroll
        for (int nt = 0; nt < 8; nt++) {
            const int c = nt * 8 + tig * 2;
            *(__half2*)(Ob + (size_t)r0 * EMB + c) =
                __floats2half2_rn(oacc[mt][nt][0] * inv0, oacc[mt][nt][1] * inv0);
            *(__half2*)(Ob + (size_t)r1 * EMB + c) =
                __floats2half2_rn(oacc[mt][nt][2] * inv1, oacc[mt][nt][3] * inv1);
        }
    }
}

// ---------------------------------------------------------------------------
// Launch
// ---------------------------------------------------------------------------
extern "C" void kernel_launch(void* const* d_in, const int* in_sizes, int n_in,
                              void* d_out, int out_size)
{
    const float* query = (const float*)d_in[0];
    const float* key   = (const float*)d_in[1];
    const float* value = (const float*)d_in[2];
    const float* bq    = (const float*)d_in[4];
    const float* bk    = (const float*)d_in[6];
    const float* bv    = (const float*)d_in[8];
    const float* bo    = (const float*)d_in[10];
    float* out = (float*)d_out;

    cudaFuncSetAttribute(gemm_qkv,
                         cudaFuncAttributeMaxDynamicSharedMemorySize,
                         GEMM_SMEM_BYTES);
    cudaFuncSetAttribute(gemm_out,
                         cudaFuncAttributeMaxDynamicSharedMemorySize,
                         GEMM_SMEM_BYTES);
    cudaFuncSetAttribute(flash_attn_mma,
                         cudaFuncAttributeMaxDynamicSharedMemorySize,
                         ATTN_SMEM_BYTES);

    // Prologue: fp16-round inputs + weights into scratch.
    round_f16_all<<<dim3(512, 7), 256>>>(
        query, key, value,
        (const float*)d_in[3], (const float*)d_in[5],
        (const float*)d_in[7], (const float*)d_in[9]);

    dim3 gqkv(EMB / GBN, MROWS / GBM, 3);   // (8, 32, 3)
    gemm_qkv<<<gqkv, 256, GEMM_SMEM_BYTES>>>(bq, bk, bv);

    dim3 gattn(SEQ / AQ, NHEAD, BATCH);  // (16, 16, 2)
    flash_attn_mma<<<gattn, 128, ATTN_SMEM_BYTES>>>();

    dim3 gout(EMB / GBN, MROWS / GBM);   // (8, 32)
    gemm_out<<<gout, 256, GEMM_SMEM_BYTES>>>(bo, out);
}

// round 16
// speedup vs baseline: 1.1576x; 1.1576x over previous
#include <cuda_runtime.h>
#include <cuda_fp16.h>
#include <math.h>
#include <stdint.h>

// Problem constants
#define BATCH 2
#define SEQ   2048
#define EMB   1024
#define NHEAD 16
#define HDIM  64
#define MROWS (BATCH*SEQ)   // 4096

// ---------------------------------------------------------------------------
// Scratch (device globals; no runtime allocation allowed) — all fp16
// ---------------------------------------------------------------------------
__device__ __half g_Q[MROWS * EMB];
__device__ __half g_K[MROWS * EMB];
__device__ __half g_VT[EMB * MROWS];   // V projection output, TRANSPOSED [emb][token]
__device__ __half g_A[MROWS * EMB];    // attention output O
// fp16-pre-rounded copies of inputs and weights
__device__ __half g_QR[MROWS * EMB];
__device__ __half g_KR[MROWS * EMB];
__device__ __half g_VR[MROWS * EMB];
__device__ __half g_WQ[EMB * EMB];
__device__ __half g_WK[EMB * EMB];
__device__ __half g_WV[EMB * EMB];
__device__ __half g_WO[EMB * EMB];

// ---------------------------------------------------------------------------
// Helpers
// ---------------------------------------------------------------------------
__device__ __forceinline__ uint32_t smem_u32(const void* p) {
    uint32_t a;
    asm("{ .reg .u64 t; cvta.to.shared.u64 t, %1; cvt.u32.u64 %0, t; }"
        : "=r"(a) : "l"(p));
    return a;
}
__device__ __forceinline__ float fexp2(float x) {
    float r;
    asm("ex2.approx.ftz.f32 %0, %1;" : "=f"(r) : "f"(x));
    return r;
}
__device__ __forceinline__ void mma_f16(float* c, const uint32_t* a, const uint32_t* b) {
    asm volatile(
        "mma.sync.aligned.m16n8k16.row.col.f32.f16.f16.f32 "
        "{%0,%1,%2,%3}, {%4,%5,%6,%7}, {%8,%9}, {%0,%1,%2,%3};"
        : "+f"(c[0]), "+f"(c[1]), "+f"(c[2]), "+f"(c[3])
        : "r"(a[0]), "r"(a[1]), "r"(a[2]), "r"(a[3]), "r"(b[0]), "r"(b[1]));
}
__device__ __forceinline__ uint32_t packh2(float x, float y) {
    __half2 h = __floats2half2_rn(x, y);
    return *(uint32_t*)&h;
}

// ldmatrix x4: four 8x8 b16 tiles (native fp16)
#define LDSM_X4(r, addr) \
    asm volatile("ldmatrix.sync.aligned.m8n8.x4.shared.b16 {%0,%1,%2,%3}, [%4];" \
        : "=r"((r)[0]), "=r"((r)[1]), "=r"((r)[2]), "=r"((r)[3]) : "r"(addr))

#define CP_ASYNC16(dst_u32, src_ptr) \
    asm volatile("cp.async.cg.shared.global [%0], [%1], 16;" \
                 :: "r"(dst_u32), "l"(src_ptr))
#define CP_COMMIT() asm volatile("cp.async.commit_group;")
#define CP_WAIT(n)  asm volatile("cp.async.wait_group %0;" :: "n"(n))

// ---------------------------------------------------------------------------
// Prologue: round tensors to fp16 (rn) into scratch. blockIdx.y picks tensor.
// ---------------------------------------------------------------------------
__global__ __launch_bounds__(256) void round_f16_all(
    const float* q, const float* k, const float* v,
    const float* wq, const float* wk, const float* wv, const float* wo)
{
    const float* src; __half* dst; int n;
    switch (blockIdx.y) {
        case 0: src = q;  dst = g_QR; n = MROWS * EMB; break;
        case 1: src = k;  dst = g_KR; n = MROWS * EMB; break;
        case 2: src = v;  dst = g_VR; n = MROWS * EMB; break;
        case 3: src = wq; dst = g_WQ; n = EMB * EMB;   break;
        case 4: src = wk; dst = g_WK; n = EMB * EMB;   break;
        case 5: src = wv; dst = g_WV; n = EMB * EMB;   break;
        default: src = wo; dst = g_WO; n = EMB * EMB;  break;
    }
    int n4 = n >> 2;
    for (int i = blockIdx.x * blockDim.x + threadIdx.x; i < n4;
         i += gridDim.x * blockDim.x) {
        float4 x = ((const float4*)src)[i];
        __half2* d = (__half2*)(dst + (size_t)i * 4);
        d[0] = __floats2half2_rn(x.x, x.y);
        d[1] = __floats2half2_rn(x.z, x.w);
    }
}

// ---------------------------------------------------------------------------
// GEMM core (fp16 operands, fp32 accum): C = A[M,K] @ W[N,K]^T + bias.
// 128x128x64 tile, 256 thr, 3-stage cp.async ring, single barrier per chunk,
// next-stage loads issued MID-CHUNK. mode: 0 fp32 C, 1 fp16 C, 2 fp16 C^T.
// ---------------------------------------------------------------------------
#define GBM 128
#define GBN 128
#define GBK 64
#define PADH 72                                   // halfs per smem row
#define GSTG_HALFS (2 * GBM * PADH)               // A+B per stage = 18432
#define GEMM_SMEM_BYTES (3 * GSTG_HALFS * 2)      // 110592

__device__ __forceinline__ void gemm_core(
    const __half* __restrict__ A, const __half* __restrict__ W,
    const float* __restrict__ bias, float* __restrict__ Cf,
    __half* __restrict__ Ch, int mode)
{
    extern __shared__ __half hsmem[];
    const int M = MROWS, N = EMB, K = EMB;

    const int tid  = threadIdx.x;
    const int lane = tid & 31;
    const int warp = tid >> 5;
    const int bm = blockIdx.y * GBM;
    const int bn = blockIdx.x * GBN;

    const int wm = (warp >> 2) * 64;
    const int wn = (warp & 3) * 32;
    const int gid = lane >> 2;
    const int tig = lane & 3;

    // ldmatrix per-lane half offsets
    const int aoff = (wm + (lane & 15)) * PADH + (lane >> 4) * 8;
    const int boff = (wn + (lane & 7)) * PADH + (lane >> 3) * 8;

    float acc[4][4][4];
#pragma unroll
    for (int mt = 0; mt < 4; mt++)
#pragma unroll
        for (int nt = 0; nt < 4; nt++)
#pragma unroll
            for (int r = 0; r < 4; r++) acc[mt][nt][r] = 0.f;

    auto load_stage = [&](int s, int k0) {
        __half* As = hsmem + s * GSTG_HALFS;
        __half* Bs = As + GBM * PADH;
#pragma unroll
        for (int p = 0; p < 4; p++) {
            int idx = tid + p * 256;        // 0..1023
            int row = idx >> 3;             // 0..127
            int c   = (idx & 7) * 8;        // halfs 0..56
            CP_ASYNC16(smem_u32(As + row * PADH + c),
                       A + (size_t)(bm + row) * K + k0 + c);
            CP_ASYNC16(smem_u32(Bs + row * PADH + c),
                       W + (size_t)(bn + row) * K + k0 + c);
        }
        CP_COMMIT();
    };

    auto compute_half = [&](uint32_t abase, uint32_t bbase, int ks2) {
        uint32_t bfr[4][4];
#pragma unroll
        for (int nt = 0; nt < 4; nt++)
            LDSM_X4(bfr[nt], bbase + 2u * (boff + nt * 8 * PADH + ks2 * 32));
#pragma unroll
        for (int ksl = 0; ksl < 2; ksl++) {
            uint32_t afr[4][4];
#pragma unroll
            for (int mt = 0; mt < 4; mt++)
                LDSM_X4(afr[mt],
                        abase + 2u * (aoff + mt * 16 * PADH + ks2 * 32 + ksl * 16));
#pragma unroll
            for (int mt = 0; mt < 4; mt++)
#pragma unroll
                for (int nt = 0; nt < 4; nt++)
                    mma_f16(acc[mt][nt], afr[mt], &bfr[nt][ksl * 2]);
        }
    };

    const int nchunk = K / GBK;   // 16
    load_stage(0, 0);
    load_stage(1, GBK);

    for (int i = 0; i < nchunk; i++) {
        CP_WAIT(1);
        __syncthreads();
        const uint32_t abase = smem_u32(hsmem + (i % 3) * GSTG_HALFS);
        const uint32_t bbase = abase + GBM * PADH * 2;

        compute_half(abase, bbase, 0);
        if (i + 2 < nchunk) load_stage((i + 2) % 3, (i + 2) * GBK);
        compute_half(abase, bbase, 1);
    }

#pragma unroll
    for (int nt = 0; nt < 4; nt++) {
        const int c0 = bn + wn + nt * 8 + tig * 2;
        const float b0 = bias[c0], b1 = bias[c0 + 1];
#pragma unroll
        for (int mt = 0; mt < 4; mt++) {
            const int r0 = bm + wm + mt * 16 + gid;
            float2 v0 = make_float2(acc[mt][nt][0] + b0, acc[mt][nt][1] + b1);
            float2 v1 = make_float2(acc[mt][nt][2] + b0, acc[mt][nt][3] + b1);
            if (mode == 0) {
                *(float2*)(Cf + (size_t)r0 * N + c0) = v0;
                *(float2*)(Cf + (size_t)(r0 + 8) * N + c0) = v1;
            } else if (mode == 1) {
                *(__half2*)(Ch + (size_t)r0 * N + c0) = __floats2half2_rn(v0.x, v0.y);
                *(__half2*)(Ch + (size_t)(r0 + 8) * N + c0) = __floats2half2_rn(v1.x, v1.y);
            } else {   // transposed: C[col][row], ldc = M
                Ch[(size_t)c0 * M + r0]           = __float2half_rn(v0.x);
                Ch[(size_t)(c0 + 1) * M + r0]     = __float2half_rn(v0.y);
                Ch[(size_t)c0 * M + r0 + 8]       = __float2half_rn(v1.x);
                Ch[(size_t)(c0 + 1) * M + r0 + 8] = __float2half_rn(v1.y);
            }
        }
    }
}

// Fused Q/K/V projection: blockIdx.z selects tensor.
__global__ __launch_bounds__(256, 2) void gemm_qkv(
    const float* __restrict__ bq, const float* __restrict__ bk,
    const float* __restrict__ bv)
{
    switch (blockIdx.z) {
        case 0: gemm_core(g_QR, g_WQ, bq, nullptr, g_Q, 1); break;
        case 1: gemm_core(g_KR, g_WK, bk, nullptr, g_K, 1); break;
        default: gemm_core(g_VR, g_WV, bv, nullptr, g_VT, 2); break;
    }
}

// Output projection (fp32 out).
__global__ __launch_bounds__(256, 2) void gemm_out(
    const float* __restrict__ bo, float* __restrict__ out)
{
    gemm_core(g_A, g_WO, bo, out, nullptr, 0);
}

// ---------------------------------------------------------------------------
// Flash attention, mma.sync fp16 (fp32 accum), 3-slot KV ring, single barrier
// per tile, KV refill issued BETWEEN the two S-mma halves (mid-phase), P kept
// in registers (S C-frag == PV A-frag). 128 threads, 4 warps, 2 CTAs/SM.
// Slot: K rows [0,64) key-major; V^T rows [64,128) hd-major. Q stages slot2.
// ---------------------------------------------------------------------------
#define AQ   128
#define AKV  64
#define APADH 72
#define SLOT_HALFS (128 * APADH)                // 9216 halfs = 18432 B
#define ATTN_SMEM_BYTES (3 * SLOT_HALFS * 2)    // 55296

__global__ __launch_bounds__(128, 2) void flash_attn_mma()
{
    extern __shared__ __half hdsm[];

    const int qt = blockIdx.x;
    const int h  = blockIdx.y;
    const int b  = blockIdx.z;

    const __half* Qb = g_Q + ((size_t)b * SEQ + qt * AQ) * EMB + h * HDIM;
    const __half* Kb = g_K + (size_t)b * SEQ * EMB + h * HDIM;
    const __half* Vtb = g_VT + (size_t)(h * HDIM) * MROWS + (size_t)b * SEQ;
    __half*       Ob = g_A + ((size_t)b * SEQ + qt * AQ) * EMB + h * HDIM;

    const int tid  = threadIdx.x;
    const int lane = tid & 31;
    const int warp = tid >> 5;
    const int gid  = lane >> 2;
    const int tig  = lane & 3;
    const int wm   = warp * 32;

    // ldmatrix per-lane half offsets
    const int aoff = (wm + (lane & 15)) * APADH + (lane >> 4) * 8;   // A rows (q)
    const int boff = (lane & 7) * APADH + (lane >> 3) * 8;           // B rows

    auto load_kv = [&](__half* base, int kt) {
        const __half* Kt = Kb + (size_t)kt * AKV * EMB;
        const __half* Vt = Vtb + (size_t)kt * AKV;
#pragma unroll
        for (int p = 0; p < 4; p++) {
            int idx = tid + p * 128;       // 0..511
            int row = idx >> 3;            // 0..63
            int c   = (idx & 7) * 8;       // halfs
            CP_ASYNC16(smem_u32(base + row * APADH + c),
                       Kt + (size_t)row * EMB + c);
            CP_ASYNC16(smem_u32(base + (AKV + row) * APADH + c),
                       Vt + (size_t)row * MROWS + c);
        }
        CP_COMMIT();
    };

    // Prologue: Q -> slot2, KV0 -> slot0, KV1 -> slot1 (all async).
    __half* slot2 = hdsm + 2 * SLOT_HALFS;
#pragma unroll
    for (int p = 0; p < 8; p++) {
        int idx = tid + p * 128;           // 0..1023
        int row = idx >> 3;                // 0..127
        int c   = (idx & 7) * 8;
        CP_ASYNC16(smem_u32(slot2 + row * APADH + c),
                   Qb + (size_t)row * EMB + c);
    }
    CP_COMMIT();
    load_kv(hdsm, 0);
    load_kv(hdsm + SLOT_HALFS, 1);

    CP_WAIT(2);            // Q resident
    __syncthreads();

    // Hoist Q fragments via ldmatrix; scale by softmax*log2e in fp32, repack.
    const float qscale = 0.125f * 1.4426950408889634f;
    const uint32_t qsbase = smem_u32(slot2);
    uint32_t qfr[2][4][4];
#pragma unroll
    for (int mt = 0; mt < 2; mt++)
#pragma unroll
        for (int ks = 0; ks < 4; ks++) {
            uint32_t t[4];
            LDSM_X4(t, qsbase + 2u * (aoff + mt * 16 * APADH + ks * 16));
#pragma unroll
            for (int j = 0; j < 4; j++) {
                float2 f = __half22float2(*(__half2*)&t[j]);
                qfr[mt][ks][j] = packh2(f.x * qscale, f.y * qscale);
            }
        }
    __syncthreads();       // all warps done with slot2 before KV2 refill

    float oacc[2][8][4];
#pragma unroll
    for (int mt = 0; mt < 2; mt++)
#pragma unroll
        for (int nt = 0; nt < 8; nt++)
#pragma unroll
            for (int r = 0; r < 4; r++) oacc[mt][nt][r] = 0.f;
    float mrow[2][2], lrow[2][2];
#pragma unroll
    for (int mt = 0; mt < 2; mt++) {
        mrow[mt][0] = -1e30f; mrow[mt][1] = -1e30f;
        lrow[mt][0] = 0.f;    lrow[mt][1] = 0.f;
    }

    const int ntile = SEQ / AKV;   // 32
    for (int kt = 0; kt < ntile; kt++) {
        CP_WAIT(1);        // KV_kt resident
        __syncthreads();
        const uint32_t kbase = smem_u32(hdsm + (kt % 3) * SLOT_HALFS);
        const uint32_t vbase = kbase + AKV * APADH * 2;

        // S = Q K^T (k = hd = 64 -> 2 x k32). Fragments get the LSU first;
        // KV refill for kt+2 goes between the two halves (mid-phase).
        float sacc[2][8][4];
#pragma unroll
        for (int mt = 0; mt < 2; mt++)
#pragma unroll
            for (int nt = 0; nt < 8; nt++)
#pragma unroll
                for (int r = 0; r < 4; r++) sacc[mt][nt][r] = 0.f;

#pragma unroll
        for (int ks2 = 0; ks2 < 2; ks2++) {
#pragma unroll
            for (int nt = 0; nt < 8; nt++) {
                uint32_t bf[4];
                LDSM_X4(bf, kbase + 2u * (boff + nt * 8 * APADH + ks2 * 32));
                mma_f16(sacc[0][nt], qfr[0][ks2 * 2], bf);
                mma_f16(sacc[1][nt], qfr[1][ks2 * 2], bf);
                mma_f16(sacc[0][nt], qfr[0][ks2 * 2 + 1], bf + 2);
                mma_f16(sacc[1][nt], qfr[1][ks2 * 2 + 1], bf + 2);
            }
            if (ks2 == 0 && kt + 2 < ntile)
                load_kv(hdsm + ((kt + 2) % 3) * SLOT_HALFS, kt + 2);
        }

        // Online softmax (exp2 domain, fp32) + build PV A-fragments directly.
        uint32_t pa[2][4][4];    // [mt][k16-tile][frag]
#pragma unroll
        for (int mt = 0; mt < 2; mt++) {
            float mx0 = -1e30f, mx1 = -1e30f;
#pragma unroll
            for (int nt = 0; nt < 8; nt++) {
                mx0 = fmaxf(mx0, fmaxf(sacc[mt][nt][0], sacc[mt][nt][1]));
                mx1 = fmaxf(mx1, fmaxf(sacc[mt][nt][2], sacc[mt][nt][3]));
            }
            mx0 = fmaxf(mx0, __shfl_xor_sync(0xffffffffu, mx0, 1));
            mx0 = fmaxf(mx0, __shfl_xor_sync(0xffffffffu, mx0, 2));
            mx1 = fmaxf(mx1, __shfl_xor_sync(0xffffffffu, mx1, 1));
            mx1 = fmaxf(mx1, __shfl_xor_sync(0xffffffffu, mx1, 2));

            float mn0 = fmaxf(mrow[mt][0], mx0), mn1 = fmaxf(mrow[mt][1], mx1);
            float corr0 = fexp2(mrow[mt][0] - mn0), corr1 = fexp2(mrow[mt][1] - mn1);
            float s0 = 0.f, s1 = 0.f;
#pragma unroll
            for (int nt = 0; nt < 8; nt++) {
                sacc[mt][nt][0] = fexp2(sacc[mt][nt][0] - mn0);
                sacc[mt][nt][1] = fexp2(sacc[mt][nt][1] - mn0);
                sacc[mt][nt][2] = fexp2(sacc[mt][nt][2] - mn1);
                sacc[mt][nt][3] = fexp2(sacc[mt][nt][3] - mn1);
                s0 += sacc[mt][nt][0] + sacc[mt][nt][1];
                s1 += sacc[mt][nt][2] + sacc[mt][nt][3];
            }
            s0 += __shfl_xor_sync(0xffffffffu, s0, 1);
            s0 += __shfl_xor_sync(0xffffffffu, s0, 2);
            s1 += __shfl_xor_sync(0xffffffffu, s1, 1);
            s1 += __shfl_xor_sync(0xffffffffu, s1, 2);
            lrow[mt][0] = lrow[mt][0] * corr0 + s0;  mrow[mt][0] = mn0;
            lrow[mt][1] = lrow[mt][1] * corr1 + s1;  mrow[mt][1] = mn1;
#pragma unroll
            for (int nt = 0; nt < 8; nt++) {
                oacc[mt][nt][0] *= corr0; oacc[mt][nt][1] *= corr0;
                oacc[mt][nt][2] *= corr1; oacc[mt][nt][3] *= corr1;
            }

            // PV A-fragments: S C-frag layout == PV A-frag layout.
#pragma unroll
            for (int kk = 0; kk < 4; kk++) {
                pa[mt][kk][0] = packh2(sacc[mt][2 * kk][0],     sacc[mt][2 * kk][1]);
                pa[mt][kk][1] = packh2(sacc[mt][2 * kk][2],     sacc[mt][2 * kk][3]);
                pa[mt][kk][2] = packh2(sacc[mt][2 * kk + 1][0], sacc[mt][2 * kk + 1][1]);
                pa[mt][kk][3] = packh2(sacc[mt][2 * kk + 1][2], sacc[mt][2 * kk + 1][3]);
            }
        }

        // O += P V : A = pa (registers), B = V^T (hd-major) via ldmatrix.
#pragma unroll
        for (int ks2 = 0; ks2 < 2; ks2++) {
#pragma unroll
            for (int nt = 0; nt < 8; nt++) {
                uint32_t vf[4];
                LDSM_X4(vf, vbase + 2u * (boff + nt * 8 * APADH + ks2 * 32));
                mma_f16(oacc[0][nt], pa[0][2 * ks2], vf);
                mma_f16(oacc[1][nt], pa[1][2 * ks2], vf);
                mma_f16(oacc[0][nt], pa[0][2 * ks2 + 1], vf + 2);
                mma_f16(oacc[1][nt], pa[1][2 * ks2 + 1], vf + 2);
            }
        }
        // No bottom barrier: next iteration's top barrier carries ring safety.
    }

    // Epilogue: normalize, round to fp16 (feeds final GEMM), write.
#pragma unroll
    for (int mt = 0; mt < 2; mt++) {
        const float inv0 = 1.0f / lrow[mt][0], inv1 = 1.0f / lrow[mt][1];
        const int r0 = wm + mt * 16 + gid, r1 = r0 + 8;
#pragma unroll
        for (int nt = 0; nt < 8; nt++) {
            const int c = nt * 8 + tig * 2;
            *(__half2*)(Ob + (size_t)r0 * EMB + c) =
                __floats2half2_rn(oacc[mt][nt][0] * inv0, oacc[mt][nt][1] * inv0);
            *(__half2*)(Ob + (size_t)r1 * EMB + c) =
                __floats2half2_rn(oacc[mt][nt][2] * inv1, oacc[mt][nt][3] * inv1);
        }
    }
}

// ---------------------------------------------------------------------------
// Launch
// ---------------------------------------------------------------------------
extern "C" void kernel_launch(void* const* d_in, const int* in_sizes, int n_in,
                              void* d_out, int out_size)
{
    const float* query = (const float*)d_in[0];
    const float* key   = (const float*)d_in[1];
    const float* value = (const float*)d_in[2];
    const float* bq    = (const float*)d_in[4];
    const float* bk    = (const float*)d_in[6];
    const float* bv    = (const float*)d_in[8];
    const float* bo    = (const float*)d_in[10];
    float* out = (float*)d_out;

    cudaFuncSetAttribute(gemm_qkv,
                         cudaFuncAttributeMaxDynamicSharedMemorySize,
                         GEMM_SMEM_BYTES);
    cudaFuncSetAttribute(gemm_out,
                         cudaFuncAttributeMaxDynamicSharedMemorySize,
                         GEMM_SMEM_BYTES);
    cudaFuncSetAttribute(flash_attn_mma,
                         cudaFuncAttributeMaxDynamicSharedMemorySize,
                         ATTN_SMEM_BYTES);

    // Prologue: fp16-round inputs + weights into scratch.
    round_f16_all<<<dim3(512, 7), 256>>>(
        query, key, value,
        (const float*)d_in[3], (const float*)d_in[5],
        (const float*)d_in[7], (const float*)d_in[9]);

    dim3 gqkv(EMB / GBN, MROWS / GBM, 3);   // (8, 32, 3)
    gemm_qkv<<<gqkv, 256, GEMM_SMEM_BYTES>>>(bq, bk, bv);

    dim3 gattn(SEQ / AQ, NHEAD, BATCH);  // (16, 16, 2)
    flash_attn_mma<<<gattn, 128, ATTN_SMEM_BYTES>>>();

    dim3 gout(EMB / GBN, MROWS / GBM);   // (8, 32)
    gemm_out<<<gout, 256, GEMM_SMEM_BYTES>>>(bo, out);
}